// round 12
// baseline (speedup 1.0000x reference)
#include <cuda_runtime.h>
#include <cuda_fp16.h>
#include <cstdint>

// Problem shape (fixed by dataset): out[M,N] = x[M,K] @ sign(w[K,N]) + b[N]
#define GM_M 8192
#define GM_K 4096
#define GM_N 4096

// Scratch (allocation-free rule: __device__ globals)
__device__ __align__(256) __half g_xh[(size_t)GM_M * GM_K];  // x in fp16, row-major [M,K]
__device__ __align__(256) __half g_wh[(size_t)GM_N * GM_K];  // sign(w) in fp16, K-major [N,K]

// ---------------------------------------------------------------------------
// PTX helpers (base sm_103 target safe: cp.async / ldmatrix / mma.sync only)
// ---------------------------------------------------------------------------
__device__ __forceinline__ uint32_t smem_u32(const void* p) {
    uint32_t a;
    asm("{ .reg .u64 t; cvta.to.shared.u64 t, %1; cvt.u32.u64 %0, t; }" : "=r"(a) : "l"(p));
    return a;
}

__device__ __forceinline__ void cp_async16(uint32_t dst, const void* src) {
    asm volatile("cp.async.cg.shared.global [%0], [%1], 16;" :: "r"(dst), "l"(src));
}
__device__ __forceinline__ void cp_commit() {
    asm volatile("cp.async.commit_group;");
}
template <int N>
__device__ __forceinline__ void cp_wait() {
    asm volatile("cp.async.wait_group %0;" :: "n"(N));
}

__device__ __forceinline__ void ldsm_x4(uint32_t& r0, uint32_t& r1, uint32_t& r2, uint32_t& r3,
                                        uint32_t addr) {
    asm volatile("ldmatrix.sync.aligned.m8n8.x4.shared.b16 {%0,%1,%2,%3}, [%4];"
                 : "=r"(r0), "=r"(r1), "=r"(r2), "=r"(r3) : "r"(addr));
}

__device__ __forceinline__ void mma_16816(float& c0, float& c1, float& c2, float& c3,
                                          uint32_t a0, uint32_t a1, uint32_t a2, uint32_t a3,
                                          uint32_t b0, uint32_t b1) {
    asm volatile(
        "mma.sync.aligned.m16n8k16.row.col.f32.f16.f16.f32 "
        "{%0,%1,%2,%3}, {%4,%5,%6,%7}, {%8,%9}, {%0,%1,%2,%3};"
        : "+f"(c0), "+f"(c1), "+f"(c2), "+f"(c3)
        : "r"(a0), "r"(a1), "r"(a2), "r"(a3), "r"(b0), "r"(b1));
}

// Canonical SW128 swizzle for 128B rows (BK=64 fp16): seg ^ (row & 7).
// Conflict-free for quarter-warp STS.128 phases (one row, 8 distinct segs)
// and every ldmatrix 8-row phase (8 consecutive rows, same seg -> 8 perms).
__device__ __forceinline__ uint32_t swz128(uint32_t row, uint32_t seg) {
    return row * 128u + ((seg ^ (row & 7u)) * 16u);
}

// ---------------------------------------------------------------------------
// Fused prep kernel:
//   blocks [0, XB)      : x fp32 -> g_xh fp16 (grid-stride float4)
//   blocks [XB, XB+WB)  : g_wh[n,k] = sign(w[k,n]) fp16 (32x32 tiled transpose)
// ---------------------------------------------------------------------------
#define PREP_XB 4096
__global__ void prep_kernel(const float4* __restrict__ x, int n4,
                            const float* __restrict__ w, int K, int N) {
    __shared__ float tile[32][33];
    if (blockIdx.x < PREP_XB) {
        __half2* out = reinterpret_cast<__half2*>(g_xh);
        for (int i = blockIdx.x * blockDim.x + threadIdx.x; i < n4; i += PREP_XB * blockDim.x) {
            float4 v = x[i];
            out[2 * i]     = __floats2half2_rn(v.x, v.y);
            out[2 * i + 1] = __floats2half2_rn(v.z, v.w);
        }
    } else {
        int bid = blockIdx.x - PREP_XB;
        int n0 = (bid & ((N / 32) - 1)) * 32;
        int k0 = (bid / (N / 32)) * 32;
        int tx = threadIdx.x & 31, ty = threadIdx.x >> 5;
#pragma unroll
        for (int j = 0; j < 32; j += 8)
            tile[ty + j][tx] = w[(size_t)(k0 + ty + j) * N + (n0 + tx)];
        __syncthreads();
#pragma unroll
        for (int j = 0; j < 32; j += 8) {
            float v = tile[tx][ty + j];  // = w[k0+tx][n0+ty+j]
            float s = (v > 0.0f) ? 1.0f : ((v < 0.0f) ? -1.0f : 0.0f);
            g_wh[(size_t)(n0 + ty + j) * K + (k0 + tx)] = __float2half_rn(s);
        }
    }
}

// ---------------------------------------------------------------------------
// GEMM: 128x128 CTA tile, BK=64, 3-stage cp.async pipeline, HMMA m16n8k16.
// 4 warps in a 2x2 grid; each warp computes 64x64 (4 m16 x 8 n8 tiles).
// Fragments double-buffered across the 4 k16 steps of each chunk.
// All shapes compile-time: cp.async/ldmatrix addressing folds to base+imm.
// ---------------------------------------------------------------------------
#define BM 128
#define BN 128
#define BK 64
#define STAGES 3
#define A_BYTES (BM * BK * 2)                 // 16 KB
#define B_BYTES (BN * BK * 2)                 // 16 KB
#define STAGE_BYTES (A_BYTES + B_BYTES)       // 32 KB
#define SMEM_DYN (STAGES * STAGE_BYTES + 256)
// gmem byte stride between j-groups of 16 rows (row stride = GM_K halves)
#define J_STRIDE ((size_t)16 * GM_K * 2)

// 16 cp.async per thread: dst = stage + dstOff + j*2048, src = ptr + j*J_STRIDE
__device__ __forceinline__ void load_chunk(uint32_t stage, uint32_t dstOff,
                                           const char* srcA, const char* srcB) {
#pragma unroll
    for (int j = 0; j < 8; ++j) {
        cp_async16(stage + dstOff + j * 2048, srcA + (size_t)j * J_STRIDE);
        cp_async16(stage + A_BYTES + dstOff + j * 2048, srcB + (size_t)j * J_STRIDE);
    }
}

__device__ __forceinline__ void load_frags(uint32_t aBase, uint32_t bBase, int s,
                                           int warp_m, int warp_n, int lr, int g,
                                           uint32_t a[4][4], uint32_t b[8][2]) {
    const uint32_t sb = 2u * s;
#pragma unroll
    for (int tm = 0; tm < 4; ++tm) {
        uint32_t row = warp_m + tm * 16 + lr + (g & 1) * 8;
        uint32_t seg = sb + (g >> 1);
        ldsm_x4(a[tm][0], a[tm][1], a[tm][2], a[tm][3], aBase + swz128(row, seg));
    }
#pragma unroll
    for (int tb = 0; tb < 4; ++tb) {
        uint32_t row = warp_n + tb * 16 + lr + (g >> 1) * 8;
        uint32_t seg = sb + (g & 1);
        ldsm_x4(b[2 * tb][0], b[2 * tb][1], b[2 * tb + 1][0], b[2 * tb + 1][1],
                bBase + swz128(row, seg));
    }
}

__global__ void __launch_bounds__(128, 2)
gemm_bin_kernel(const float* __restrict__ bias, float* __restrict__ out) {
    extern __shared__ char dynsmem[];
    const uint32_t smem = (smem_u32(dynsmem) + 255u) & ~255u;

    const int tid = threadIdx.x;
    const int wid = tid >> 5;
    const int lane = tid & 31;
    const int m0 = blockIdx.y * BM;
    const int n0 = blockIdx.x * BN;
    const int warp_m = (wid >> 1) * 64;  // 0 / 64
    const int warp_n = (wid & 1) * 64;   // 0 / 64
    const int lr = lane & 7;
    const int g  = lane >> 3;

    // Per-thread cp.async constants: c = tid + j*128 -> row = (tid>>3)+j*16,
    // seg = tid&7 (j-invariant); row&7 = (tid>>3)&7 (j-invariant) so the
    // swizzled dst offset is dstOff + j*2048 with dstOff fixed per thread.
    const uint32_t row0 = (uint32_t)tid >> 3;
    const uint32_t seg0 = (uint32_t)tid & 7;
    const uint32_t dstOff = row0 * 128u + ((seg0 ^ (row0 & 7u)) << 4);
    // gmem source pointers for the NEXT chunk to load; advance 128 B/chunk.
    const char* srcA = (const char*)(g_xh + ((size_t)(m0 + row0) * GM_K + seg0 * 8));
    const char* srcB = (const char*)(g_wh + ((size_t)(n0 + row0) * GM_K + seg0 * 8));

    float acc[4][8][4];
#pragma unroll
    for (int i = 0; i < 4; ++i)
#pragma unroll
        for (int j = 0; j < 8; ++j)
#pragma unroll
            for (int r = 0; r < 4; ++r) acc[i][j][r] = 0.0f;

    constexpr int nk = GM_K / BK;  // 64

    // Prologue: fill STAGES-1 buffers
#pragma unroll
    for (int s = 0; s < STAGES - 1; ++s) {
        load_chunk(smem + s * STAGE_BYTES, dstOff, srcA, srcB);
        cp_commit();
        srcA += BK * 2;
        srcB += BK * 2;
    }

    uint32_t a[2][4][4], b[2][8][2];

    for (int kt = 0; kt < nk; ++kt) {
        cp_wait<STAGES - 2>();
        __syncthreads();  // stage kt ready AND all reads of stage kt-1 finished

        const uint32_t aBase = smem + (kt % STAGES) * STAGE_BYTES;
        const uint32_t bBase = aBase + A_BYTES;

        // Fragments for step 0 first, so ldsm latency overlaps prefetch issue
        load_frags(aBase, bBase, 0, warp_m, warp_n, lr, g, a[0], b[0]);

        // Prefetch chunk kt+STAGES-1 into the buffer read at kt-1 (free now)
        if (kt + STAGES - 1 < nk) {
            load_chunk(smem + ((kt + STAGES - 1) % STAGES) * STAGE_BYTES, dstOff, srcA, srcB);
            srcA += BK * 2;
            srcB += BK * 2;
        }
        cp_commit();  // uniform group accounting

#pragma unroll
        for (int s = 0; s < 4; ++s) {  // four k16 steps per BK=64 chunk
            if (s < 3)
                load_frags(aBase, bBase, s + 1, warp_m, warp_n, lr, g,
                           a[(s + 1) & 1], b[(s + 1) & 1]);
            const int cur = s & 1;
#pragma unroll
            for (int tm = 0; tm < 4; ++tm)
#pragma unroll
                for (int tn = 0; tn < 8; ++tn)
                    mma_16816(acc[tm][tn][0], acc[tm][tn][1], acc[tm][tn][2], acc[tm][tn][3],
                              a[cur][tm][0], a[cur][tm][1], a[cur][tm][2], a[cur][tm][3],
                              b[cur][tn][0], b[cur][tn][1]);
        }
        // no trailing sync: top-of-next-iteration sync orders reads vs overwrite
    }

    // Epilogue: c-fragment (r=lane/4, c=(lane%4)*2) + bias, float2 stores
    const int qr = lane >> 2;
    const int qc = (lane & 3) * 2;
#pragma unroll
    for (int tm = 0; tm < 4; ++tm) {
#pragma unroll
        for (int tn = 0; tn < 8; ++tn) {
            int n = n0 + warp_n + tn * 8 + qc;
            int m = m0 + warp_m + tm * 16 + qr;
            float2 bv = *reinterpret_cast<const float2*>(bias + n);
            float2 v0 = make_float2(acc[tm][tn][0] + bv.x, acc[tm][tn][1] + bv.y);
            float2 v1 = make_float2(acc[tm][tn][2] + bv.x, acc[tm][tn][3] + bv.y);
            *reinterpret_cast<float2*>(out + (size_t)m * GM_N + n) = v0;
            *reinterpret_cast<float2*>(out + (size_t)(m + 8) * GM_N + n) = v1;
        }
    }
}

// ---------------------------------------------------------------------------
// Launch
// ---------------------------------------------------------------------------
extern "C" void kernel_launch(void* const* d_in, const int* in_sizes, int n_in,
                              void* d_out, int out_size) {
    const float* x = (const float*)d_in[0];   // [M, K] fp32
    const float* w = (const float*)d_in[1];   // [K, N] fp32
    const float* b = (const float*)d_in[2];   // [N]    fp32
    float* out = (float*)d_out;               // [M, N] fp32

    const int N = in_sizes[2];                // filters
    const int K = in_sizes[1] / N;            // d_in
    const int M = in_sizes[0] / K;            // n_tokens

    // 1) fused prep: x -> fp16, sign(w) -> fp16 transposed [N,K]
    int n4 = (M * K) / 4;
    int wblocks = (N / 32) * (K / 32);
    prep_kernel<<<PREP_XB + wblocks, 256>>>(reinterpret_cast<const float4*>(x), n4, w, K, N);

    // 2) HMMA tensor-core GEMM (compile-time shape)
    cudaFuncSetAttribute(gemm_bin_kernel, cudaFuncAttributeMaxDynamicSharedMemorySize, SMEM_DYN);
    dim3 grid(GM_N / BN, GM_M / BM);
    gemm_bin_kernel<<<grid, 128, SMEM_DYN>>>(b, out);
}

// round 13
// speedup vs baseline: 1.0021x; 1.0021x over previous
#include <cuda_runtime.h>
#include <cuda_fp16.h>
#include <cstdint>

// Problem shape (fixed by dataset): out[M,N] = x[M,K] @ sign(w[K,N]) + b[N]
#define GM_M 8192
#define GM_K 4096
#define GM_N 4096

// Scratch (allocation-free rule: __device__ globals)
__device__ __align__(256) __half g_xh[(size_t)GM_M * GM_K];  // x in fp16, row-major [M,K]
__device__ __align__(256) __half g_wh[(size_t)GM_N * GM_K];  // sign(w) in fp16, K-major [N,K]

// ---------------------------------------------------------------------------
// PTX helpers (base sm_103 target safe: cp.async / ldmatrix / mma.sync only)
// ---------------------------------------------------------------------------
__device__ __forceinline__ uint32_t smem_u32(const void* p) {
    uint32_t a;
    asm("{ .reg .u64 t; cvta.to.shared.u64 t, %1; cvt.u32.u64 %0, t; }" : "=r"(a) : "l"(p));
    return a;
}

__device__ __forceinline__ void cp_async16(uint32_t dst, const void* src) {
    asm volatile("cp.async.cg.shared.global [%0], [%1], 16;" :: "r"(dst), "l"(src));
}
__device__ __forceinline__ void cp_commit() {
    asm volatile("cp.async.commit_group;");
}
template <int N>
__device__ __forceinline__ void cp_wait() {
    asm volatile("cp.async.wait_group %0;" :: "n"(N));
}

__device__ __forceinline__ void ldsm_x4(uint32_t& r0, uint32_t& r1, uint32_t& r2, uint32_t& r3,
                                        uint32_t addr) {
    asm volatile("ldmatrix.sync.aligned.m8n8.x4.shared.b16 {%0,%1,%2,%3}, [%4];"
                 : "=r"(r0), "=r"(r1), "=r"(r2), "=r"(r3) : "r"(addr));
}

__device__ __forceinline__ void mma_16816(float& c0, float& c1, float& c2, float& c3,
                                          uint32_t a0, uint32_t a1, uint32_t a2, uint32_t a3,
                                          uint32_t b0, uint32_t b1) {
    asm volatile(
        "mma.sync.aligned.m16n8k16.row.col.f32.f16.f16.f32 "
        "{%0,%1,%2,%3}, {%4,%5,%6,%7}, {%8,%9}, {%0,%1,%2,%3};"
        : "+f"(c0), "+f"(c1), "+f"(c2), "+f"(c3)
        : "r"(a0), "r"(a1), "r"(a2), "r"(a3), "r"(b0), "r"(b1));
}

// Canonical SW128 swizzle for 128B rows (BK=64 fp16): seg ^ (row & 7).
__device__ __forceinline__ uint32_t swz128(uint32_t row, uint32_t seg) {
    return row * 128u + ((seg ^ (row & 7u)) * 16u);
}

// ---------------------------------------------------------------------------
// Fused prep kernel:
//   blocks [0, XB)      : x fp32 -> g_xh fp16 (grid-stride float4)
//   blocks [XB, XB+WB)  : g_wh[n,k] = sign(w[k,n]) fp16 (32x32 tiled transpose)
// ---------------------------------------------------------------------------
#define PREP_XB 4096
__global__ void prep_kernel(const float4* __restrict__ x, int n4,
                            const float* __restrict__ w, int K, int N) {
    __shared__ float tile[32][33];
    if (blockIdx.x < PREP_XB) {
        __half2* out = reinterpret_cast<__half2*>(g_xh);
        for (int i = blockIdx.x * blockDim.x + threadIdx.x; i < n4; i += PREP_XB * blockDim.x) {
            float4 v = x[i];
            out[2 * i]     = __floats2half2_rn(v.x, v.y);
            out[2 * i + 1] = __floats2half2_rn(v.z, v.w);
        }
    } else {
        int bid = blockIdx.x - PREP_XB;
        int n0 = (bid & ((N / 32) - 1)) * 32;
        int k0 = (bid / (N / 32)) * 32;
        int tx = threadIdx.x & 31, ty = threadIdx.x >> 5;
#pragma unroll
        for (int j = 0; j < 32; j += 8)
            tile[ty + j][tx] = w[(size_t)(k0 + ty + j) * N + (n0 + tx)];
        __syncthreads();
#pragma unroll
        for (int j = 0; j < 32; j += 8) {
            float v = tile[tx][ty + j];  // = w[k0+tx][n0+ty+j]
            float s = (v > 0.0f) ? 1.0f : ((v < 0.0f) ? -1.0f : 0.0f);
            g_wh[(size_t)(n0 + ty + j) * K + (k0 + tx)] = __float2half_rn(s);
        }
    }
}

// ---------------------------------------------------------------------------
// GEMM: 128x128 CTA tile, BK=64, 3-stage cp.async pipeline, HMMA m16n8k16.
// 4 warps in a 2x2 grid; each warp computes 64x64 (4 m16 x 8 n8 tiles).
// Fragment double-buffer carried ACROSS chunk boundaries: after the barrier
// at step 3 the next chunk's step-0 fragments are loaded, so post-barrier
// MMAs always issue straight from registers.
// ---------------------------------------------------------------------------
#define BM 128
#define BN 128
#define BK 64
#define STAGES 3
#define A_BYTES (BM * BK * 2)                 // 16 KB
#define B_BYTES (BN * BK * 2)                 // 16 KB
#define STAGE_BYTES (A_BYTES + B_BYTES)       // 32 KB
#define SMEM_DYN (STAGES * STAGE_BYTES + 256)
#define J_STRIDE ((size_t)16 * GM_K * 2)      // 16 rows of gmem

// 16 cp.async per thread: dst = stage + dstOff + j*2048, src = ptr + j*J_STRIDE
__device__ __forceinline__ void load_chunk(uint32_t stage, uint32_t dstOff,
                                           const char* srcA, const char* srcB) {
#pragma unroll
    for (int j = 0; j < 8; ++j) {
        cp_async16(stage + dstOff + j * 2048, srcA + (size_t)j * J_STRIDE);
        cp_async16(stage + A_BYTES + dstOff + j * 2048, srcB + (size_t)j * J_STRIDE);
    }
}

__device__ __forceinline__ void load_frags(uint32_t aBase, uint32_t bBase, int s,
                                           int warp_m, int warp_n, int lr, int g,
                                           uint32_t a[4][4], uint32_t b[8][2]) {
    const uint32_t sb = 2u * s;
#pragma unroll
    for (int tm = 0; tm < 4; ++tm) {
        uint32_t row = warp_m + tm * 16 + lr + (g & 1) * 8;
        uint32_t seg = sb + (g >> 1);
        ldsm_x4(a[tm][0], a[tm][1], a[tm][2], a[tm][3], aBase + swz128(row, seg));
    }
#pragma unroll
    for (int tb = 0; tb < 4; ++tb) {
        uint32_t row = warp_n + tb * 16 + lr + (g >> 1) * 8;
        uint32_t seg = sb + (g & 1);
        ldsm_x4(b[2 * tb][0], b[2 * tb][1], b[2 * tb + 1][0], b[2 * tb + 1][1],
                bBase + swz128(row, seg));
    }
}

__global__ void __launch_bounds__(128, 2)
gemm_bin_kernel(const float* __restrict__ bias, float* __restrict__ out) {
    extern __shared__ char dynsmem[];
    const uint32_t smem = (smem_u32(dynsmem) + 255u) & ~255u;

    const int tid = threadIdx.x;
    const int wid = tid >> 5;
    const int lane = tid & 31;
    const int m0 = blockIdx.y * BM;
    const int n0 = blockIdx.x * BN;
    const int warp_m = (wid >> 1) * 64;  // 0 / 64
    const int warp_n = (wid & 1) * 64;   // 0 / 64
    const int lr = lane & 7;
    const int g  = lane >> 3;

    // Per-thread cp.async constants (compile-time-shape folded addressing)
    const uint32_t row0 = (uint32_t)tid >> 3;
    const uint32_t seg0 = (uint32_t)tid & 7;
    const uint32_t dstOff = row0 * 128u + ((seg0 ^ (row0 & 7u)) << 4);
    const char* srcA = (const char*)(g_xh + ((size_t)(m0 + row0) * GM_K + seg0 * 8));
    const char* srcB = (const char*)(g_wh + ((size_t)(n0 + row0) * GM_K + seg0 * 8));

    float acc[4][8][4];
#pragma unroll
    for (int i = 0; i < 4; ++i)
#pragma unroll
        for (int j = 0; j < 8; ++j)
#pragma unroll
            for (int r = 0; r < 4; ++r) acc[i][j][r] = 0.0f;

    constexpr int nk = GM_K / BK;  // 64

    // Prologue: fill 2 stages; make chunk 0 visible; preload its step-0 frags
#pragma unroll
    for (int s = 0; s < STAGES - 1; ++s) {
        load_chunk(smem + s * STAGE_BYTES, dstOff, srcA, srcB);
        cp_commit();
        srcA += BK * 2;
        srcB += BK * 2;
    }
    cp_wait<STAGES - 2>();
    __syncthreads();

    uint32_t a[2][4][4], b[2][8][2];
    load_frags(smem, smem + A_BYTES, 0, warp_m, warp_n, lr, g, a[0], b[0]);

    for (int kt = 0; kt < nk; ++kt) {
        // Issue prefetch of chunk kt+2 into stage (kt+2)%3 (its old contents,
        // chunk kt-1, were last read before the barrier at iter kt-1).
        if (kt + 2 < nk) {
            load_chunk(smem + ((kt + 2) % STAGES) * STAGE_BYTES, dstOff, srcA, srcB);
            srcA += BK * 2;
            srcB += BK * 2;
        }
        cp_commit();  // uniform group accounting

        const uint32_t aBase = smem + (kt % STAGES) * STAGE_BYTES;
        const uint32_t bBase = aBase + A_BYTES;

#pragma unroll
        for (int s = 0; s < 4; ++s) {  // four k16 steps per BK=64 chunk
            if (s < 3) {
                load_frags(aBase, bBase, s + 1, warp_m, warp_n, lr, g,
                           a[(s + 1) & 1], b[(s + 1) & 1]);
            } else {
                // Chunk kt+1 visible after this barrier (wait<1> covers it);
                // barrier also releases stage (kt+2)%3 written next iteration.
                cp_wait<STAGES - 2>();
                __syncthreads();
            }
            const int cur = s & 1;
#pragma unroll
            for (int tm = 0; tm < 4; ++tm)
#pragma unroll
                for (int tn = 0; tn < 8; ++tn)
                    mma_16816(acc[tm][tn][0], acc[tm][tn][1], acc[tm][tn][2], acc[tm][tn][3],
                              a[cur][tm][0], a[cur][tm][1], a[cur][tm][2], a[cur][tm][3],
                              b[cur][tn][0], b[cur][tn][1]);
            if (s == 3 && kt + 1 < nk) {
                // Preload next chunk's step-0 fragments into buf[0] (parity
                // continues: consumed at s=0 of iter kt+1).
                const uint32_t aN = smem + ((kt + 1) % STAGES) * STAGE_BYTES;
                load_frags(aN, aN + A_BYTES, 0, warp_m, warp_n, lr, g, a[0], b[0]);
            }
        }
    }

    // Epilogue: hoisted bias, c-fragment (r=lane/4, c=(lane%4)*2), float2 stores
    const int qr = lane >> 2;
    const int qc = (lane & 3) * 2;
    float2 bv[8];
#pragma unroll
    for (int tn = 0; tn < 8; ++tn)
        bv[tn] = *reinterpret_cast<const float2*>(bias + n0 + warp_n + tn * 8 + qc);
#pragma unroll
    for (int tm = 0; tm < 4; ++tm) {
#pragma unroll
        for (int tn = 0; tn < 8; ++tn) {
            int n = n0 + warp_n + tn * 8 + qc;
            int m = m0 + warp_m + tm * 16 + qr;
            float2 v0 = make_float2(acc[tm][tn][0] + bv[tn].x, acc[tm][tn][1] + bv[tn].y);
            float2 v1 = make_float2(acc[tm][tn][2] + bv[tn].x, acc[tm][tn][3] + bv[tn].y);
            *reinterpret_cast<float2*>(out + (size_t)m * GM_N + n) = v0;
            *reinterpret_cast<float2*>(out + (size_t)(m + 8) * GM_N + n) = v1;
        }
    }
}

// ---------------------------------------------------------------------------
// Launch
// ---------------------------------------------------------------------------
extern "C" void kernel_launch(void* const* d_in, const int* in_sizes, int n_in,
                              void* d_out, int out_size) {
    const float* x = (const float*)d_in[0];   // [M, K] fp32
    const float* w = (const float*)d_in[1];   // [K, N] fp32
    const float* b = (const float*)d_in[2];   // [N]    fp32
    float* out = (float*)d_out;               // [M, N] fp32

    const int N = in_sizes[2];                // filters
    const int K = in_sizes[1] / N;            // d_in
    const int M = in_sizes[0] / K;            // n_tokens

    // 1) fused prep: x -> fp16, sign(w) -> fp16 transposed [N,K]
    int n4 = (M * K) / 4;
    int wblocks = (N / 32) * (K / 32);
    prep_kernel<<<PREP_XB + wblocks, 256>>>(reinterpret_cast<const float4*>(x), n4, w, K, N);

    // 2) HMMA tensor-core GEMM (compile-time shape)
    cudaFuncSetAttribute(gemm_bin_kernel, cudaFuncAttributeMaxDynamicSharedMemorySize, SMEM_DYN);
    dim3 grid(GM_N / BN, GM_M / BM);
    gemm_bin_kernel<<<grid, 128, SMEM_DYN>>>(b, out);
}